// round 2
// baseline (speedup 1.0000x reference)
#include <cuda_runtime.h>

#define FS 4096
#define FT 4096
#define NPTS (FS * 8)
#define NBLK 128
#define TPB 256

typedef unsigned long long u64;

// Scratch (allocation-free: __device__ globals)
__device__ float4 g_src_bc[FS];      // xyz, w = 0.5*|bc|^2
__device__ float4 g_tgt_bc[FT];      // xyz, w = 0.5*|bc|^2
__device__ float4 g_pts[NPTS];       // xyz, w = |pt|^2
__device__ float  g_fwd_partial[NBLK];
__device__ float  g_rev_partial[NBLK];

// ---- packed f32x2 helpers (sm_103a) ---------------------------------------
__device__ __forceinline__ u64 pk2(float a, float b) {
    u64 r; asm("mov.b64 %0,{%1,%2};" : "=l"(r) : "f"(a), "f"(b)); return r;
}
__device__ __forceinline__ u64 fma2(u64 a, u64 b, u64 c) {
    u64 d; asm("fma.rn.f32x2 %0,%1,%2,%3;" : "=l"(d) : "l"(a), "l"(b), "l"(c)); return d;
}
__device__ __forceinline__ void upk2(u64 d, float& x, float& y) {
    asm("mov.b64 {%0,%1},%2;" : "=f"(x), "=f"(y) : "l"(d));
}

// Branchless insert of (v, j) into ascending sorted-6. v >= be[5] is a no-op,
// so non-hitting lanes pass v = be[5] as a sentinel.
__device__ __forceinline__ void insert6(float v, int j, float be[6], int bi[6]) {
    bool c0 = v < be[0], c1 = v < be[1], c2 = v < be[2];
    bool c3 = v < be[3], c4 = v < be[4], c5 = v < be[5];
    be[5] = c4 ? be[4] : (c5 ? v : be[5]);
    bi[5] = c4 ? bi[4] : (c5 ? j : bi[5]);
    be[4] = c3 ? be[3] : (c4 ? v : be[4]);
    bi[4] = c3 ? bi[3] : (c4 ? j : bi[4]);
    be[3] = c2 ? be[2] : (c3 ? v : be[3]);
    bi[3] = c2 ? bi[2] : (c3 ? j : bi[3]);
    be[2] = c1 ? be[1] : (c2 ? v : be[2]);
    bi[2] = c1 ? bi[1] : (c2 ? j : bi[2]);
    be[1] = c0 ? be[0] : (c1 ? v : be[1]);
    bi[1] = c0 ? bi[0] : (c1 ? j : bi[1]);
    be[0] = c0 ? v : be[0];
    bi[0] = c0 ? j : bi[0];
}

// ---------------------------------------------------------------------------
// Kernel 1: barycenters + sampled points
// ---------------------------------------------------------------------------
__global__ void prep_kernel(const float* __restrict__ sv, const int* __restrict__ sf,
                            const float* __restrict__ tv, const int* __restrict__ tf,
                            const float* __restrict__ r1u, const float* __restrict__ r2u) {
    int i = blockIdx.x * blockDim.x + threadIdx.x;
    if (i < FS) {
        int a = sf[3*i+0], b = sf[3*i+1], c = sf[3*i+2];
        float x = (sv[3*a+0] + sv[3*b+0] + sv[3*c+0]) * (1.0f/3.0f);
        float y = (sv[3*a+1] + sv[3*b+1] + sv[3*c+1]) * (1.0f/3.0f);
        float z = (sv[3*a+2] + sv[3*b+2] + sv[3*c+2]) * (1.0f/3.0f);
        g_src_bc[i] = make_float4(x, y, z, 0.5f*(x*x + y*y + z*z));
        int ta = tf[i], tb = tf[FT + i], tc = tf[2*FT + i];
        float tx = (tv[3*ta+0] + tv[3*tb+0] + tv[3*tc+0]) * (1.0f/3.0f);
        float ty = (tv[3*ta+1] + tv[3*tb+1] + tv[3*tc+1]) * (1.0f/3.0f);
        float tz = (tv[3*ta+2] + tv[3*tb+2] + tv[3*tc+2]) * (1.0f/3.0f);
        g_tgt_bc[i] = make_float4(tx, ty, tz, 0.5f*(tx*tx + ty*ty + tz*tz));
    }
    if (i < NPTS) {
        int f = i >> 3;
        int a = sf[3*f+0], b = sf[3*f+1], c = sf[3*f+2];
        float r1 = sqrtf(r1u[i]);
        float r2 = r2u[i];
        float w1 = 1.0f - r1;
        float w2 = r1 * (1.0f - r2);
        float w3 = r1 * r2;
        float x = w1*sv[3*a+0] + w2*sv[3*b+0] + w3*sv[3*c+0];
        float y = w1*sv[3*a+1] + w2*sv[3*b+1] + w3*sv[3*c+1];
        float z = w1*sv[3*a+2] + w2*sv[3*b+2] + w3*sv[3*c+2];
        g_pts[i] = make_float4(x, y, z, x*x + y*y + z*z);
    }
}

// ---------------------------------------------------------------------------
// Kernel 2: reverse loss — per-thread point, packed-pair candidates,
// ballot-guarded branchless top-6 insertion.
// ---------------------------------------------------------------------------
__global__ void rev_kernel(const float* __restrict__ probs) {
    extern __shared__ char smem_raw[];
    float4* s_src = (float4*)smem_raw;        // FS float4 packed pairs (64 KB)
    float4* s_tgt = s_src + FS;               // FT float4 packed pairs (64 KB)
    float*  s_pr  = (float*)(s_tgt + FT);     // FS floats (16 KB)

    int tid = threadIdx.x;
    // Build pair-interleaved layout: pair t -> {x0,x1,y0,y1}, {z0,z1,w0,w1}
    for (int t = tid; t < FS/2; t += TPB) {
        float4 a = g_src_bc[2*t], b = g_src_bc[2*t+1];
        s_src[2*t]   = make_float4(a.x, b.x, a.y, b.y);
        s_src[2*t+1] = make_float4(a.z, b.z, a.w, b.w);
        float4 c = g_tgt_bc[2*t], d = g_tgt_bc[2*t+1];
        s_tgt[2*t]   = make_float4(c.x, d.x, c.y, d.y);
        s_tgt[2*t+1] = make_float4(c.z, d.z, c.w, d.w);
    }
    for (int k = tid; k < FS; k += TPB) s_pr[k] = probs[k];
    __syncthreads();

    int i     = blockIdx.x * TPB + tid;
    float4 p  = g_pts[i];                 // p.w = full |p|^2
    int sface = i >> 3;

    u64 npx = pk2(-p.x, -p.x);
    u64 npy = pk2(-p.y, -p.y);
    u64 npz = pk2(-p.z, -p.z);

    float be[6]; int bi[6];
    #pragma unroll
    for (int k = 0; k < 6; k++) { be[k] = 1e30f; bi[k] = -1; }

    // top-6 smallest e = 0.5|q|^2 - p.q over source barycenters
    #pragma unroll 4
    for (int t = 0; t < FS/2; t++) {
        float4 A = s_src[2*t], B = s_src[2*t+1];
        u64 d = fma2(npz, pk2(B.x, B.y), pk2(B.z, B.w));   // -pz*z + w
        d = fma2(npy, pk2(A.z, A.w), d);
        d = fma2(npx, pk2(A.x, A.y), d);
        float e0, e1; upk2(d, e0, e1);
        float em = fminf(e0, e1);
        unsigned bal = __ballot_sync(0xffffffffu, em < be[5]);
        if (bal) {
            bool first0 = (e0 <= e1);
            float v  = em < be[5] ? em : be[5];   // sentinel if no hit
            int  jm  = first0 ? 2*t : 2*t + 1;
            insert6(v, jm, be, bi);
            float eo = fmaxf(e0, e1);
            unsigned bal2 = __ballot_sync(0xffffffffu, eo < be[5]);
            if (bal2) {
                float v2 = eo < be[5] ? eo : be[5];
                int  jo  = first0 ? 2*t + 1 : 2*t;
                insert6(v2, jo, be, bi);
            }
        }
    }

    // min e over target barycenters (pure packed math, dual accumulators)
    float m0 = 1e30f, m1 = 1e30f;
    #pragma unroll 8
    for (int t = 0; t < FT/2; t++) {
        float4 A = s_tgt[2*t], B = s_tgt[2*t+1];
        u64 d = fma2(npz, pk2(B.x, B.y), pk2(B.z, B.w));
        d = fma2(npy, pk2(A.z, A.w), d);
        d = fma2(npx, pk2(A.x, A.y), d);
        float e0, e1; upk2(d, e0, e1);
        m0 = fminf(m0, e0);
        m1 = fminf(m1, e1);
    }
    float mte = fminf(m0, m1);

    // self-exclusion + weighted mean of valid 5
    int selfpos = 6;
    #pragma unroll
    for (int k = 0; k < 6; k++) if (bi[k] == sface) selfpos = k;
    float s5 = 0.0f;
    #pragma unroll
    for (int k = 0; k < 6; k++) {
        bool inc = (k != selfpos) && (k < 5 || selfpos <= 5);
        if (inc) {
            float d = fmaxf(fmaf(2.0f, be[k], p.w), 0.0f);
            s5 += s_pr[bi[k]] * d;
        }
    }
    float pp   = s_pr[sface];
    float mind = fmaxf(fmaf(2.0f, mte, p.w), 0.0f);
    float val  = fmaf(pp, mind, (1.0f - pp) * (s5 * 0.2f));

    __shared__ float red[TPB];
    red[tid] = val;
    __syncthreads();
    #pragma unroll
    for (int s = TPB/2; s > 0; s >>= 1) {
        if (tid < s) red[tid] += red[tid + s];
        __syncthreads();
    }
    if (tid == 0) g_rev_partial[blockIdx.x] = red[0];
}

// ---------------------------------------------------------------------------
// Kernel 3: forward loss (8 lanes per source face)
// ---------------------------------------------------------------------------
__global__ void fwd_kernel(const float* __restrict__ probs) {
    extern __shared__ float4 s_tgt[];   // FT float4 = 64 KB
    int tid = threadIdx.x;
    for (int k = tid; k < FT; k += TPB) s_tgt[k] = g_tgt_bc[k];
    __syncthreads();

    int gid   = blockIdx.x * TPB + tid;
    int face  = gid >> 3;
    int chunk = gid & 7;
    float4 p  = g_src_bc[face];           // p.w = 0.5*|p|^2

    float beste = 1e30f;
    #pragma unroll 8
    for (int t = 0; t < FT/8; t++) {
        float4 q  = s_tgt[chunk + 8*t];
        float e = fmaf(-p.x, q.x, fmaf(-p.y, q.y, fmaf(-p.z, q.z, q.w)));
        beste = fminf(beste, e);
    }
    beste = fminf(beste, __shfl_xor_sync(0xffffffffu, beste, 1));
    beste = fminf(beste, __shfl_xor_sync(0xffffffffu, beste, 2));
    beste = fminf(beste, __shfl_xor_sync(0xffffffffu, beste, 4));

    float contrib = 0.0f;
    if (chunk == 0) {
        float d = fmaxf(2.0f * (p.w + beste), 0.0f);
        contrib = probs[face] * d;
    }
    __shared__ float red[TPB];
    red[tid] = contrib;
    __syncthreads();
    #pragma unroll
    for (int s = TPB/2; s > 0; s >>= 1) {
        if (tid < s) red[tid] += red[tid + s];
        __syncthreads();
    }
    if (tid == 0) g_fwd_partial[blockIdx.x] = red[0];
}

// ---------------------------------------------------------------------------
// Kernel 4: deterministic final reduction
// ---------------------------------------------------------------------------
__global__ void final_kernel(float* __restrict__ out) {
    __shared__ float red[TPB];
    int t = threadIdx.x;
    float v = 0.0f;
    if (t < NBLK) v = g_fwd_partial[t] + g_rev_partial[t];
    red[t] = v;
    __syncthreads();
    #pragma unroll
    for (int s = TPB/2; s > 0; s >>= 1) {
        if (t < s) red[t] += red[t + s];
        __syncthreads();
    }
    if (t == 0) out[0] = red[0];
}

extern "C" void kernel_launch(void* const* d_in, const int* in_sizes, int n_in,
                              void* d_out, int out_size) {
    const float* sv    = (const float*)d_in[0];
    const int*   sf    = (const int*)  d_in[1];
    const float* tv    = (const float*)d_in[2];
    const int*   tf    = (const int*)  d_in[3];
    const float* probs = (const float*)d_in[4];
    const float* r1u   = (const float*)d_in[5];
    const float* r2u   = (const float*)d_in[6];

    const size_t fwd_smem = (size_t)FT * sizeof(float4);
    const size_t rev_smem = (size_t)(FS + FT) * sizeof(float4) + (size_t)FS * sizeof(float);
    cudaFuncSetAttribute(fwd_kernel, cudaFuncAttributeMaxDynamicSharedMemorySize, (int)fwd_smem);
    cudaFuncSetAttribute(rev_kernel, cudaFuncAttributeMaxDynamicSharedMemorySize, (int)rev_smem);

    // rev second so ncu (-s 5 -c 1) captures it on the 6th launch
    prep_kernel<<<NPTS / TPB, TPB>>>(sv, sf, tv, tf, r1u, r2u);
    rev_kernel <<<NBLK, TPB, rev_smem>>>(probs);
    fwd_kernel <<<NBLK, TPB, fwd_smem>>>(probs);
    final_kernel<<<1, TPB>>>((float*)d_out);
}

// round 3
// speedup vs baseline: 1.3357x; 1.3357x over previous
#include <cuda_runtime.h>

#define FS 4096
#define FT 4096
#define NPTS (FS * 8)
#define FWD_BLK 128
#define REV_BLK 256
#define REV_TPB 128
#define TPB 256

typedef unsigned long long u64;

// Scratch (allocation-free: __device__ globals)
__device__ float4 g_src_bc[FS];      // xyz, w = 0.5*|bc|^2
__device__ float4 g_tgt_bc[FT];      // xyz, w = 0.5*|bc|^2
__device__ float4 g_pts[NPTS];       // xyz, w = |pt|^2
__device__ float  g_mte[NPTS];       // per-point min-e over targets
__device__ float  g_fwd_partial[FWD_BLK];
__device__ float  g_rev_partial[REV_BLK];

// ---- packed f32x2 helpers (sm_103a) ---------------------------------------
__device__ __forceinline__ u64 pk2(float a, float b) {
    u64 r; asm("mov.b64 %0,{%1,%2};" : "=l"(r) : "f"(a), "f"(b)); return r;
}
__device__ __forceinline__ u64 fma2(u64 a, u64 b, u64 c) {
    u64 d; asm("fma.rn.f32x2 %0,%1,%2,%3;" : "=l"(d) : "l"(a), "l"(b), "l"(c)); return d;
}
__device__ __forceinline__ void upk2(u64 d, float& x, float& y) {
    asm("mov.b64 {%0,%1},%2;" : "=f"(x), "=f"(y) : "l"(d));
}

// sorted ascending insert (strict <), matches top_k lowest-index tie-break
// when candidates are processed in ascending j order.
__device__ __forceinline__ void try_insert(float e, int j, float be[6], int bi[6]) {
    if (e < be[5]) {
        be[5] = e; bi[5] = j;
        #pragma unroll
        for (int k = 5; k > 0; --k) {
            if (be[k] < be[k-1]) {
                float te = be[k]; be[k] = be[k-1]; be[k-1] = te;
                int   ti = bi[k]; bi[k] = bi[k-1]; bi[k-1] = ti;
            }
        }
    }
}

// ---------------------------------------------------------------------------
// Kernel 1: barycenters + sampled points
// ---------------------------------------------------------------------------
__global__ void prep_kernel(const float* __restrict__ sv, const int* __restrict__ sf,
                            const float* __restrict__ tv, const int* __restrict__ tf,
                            const float* __restrict__ r1u, const float* __restrict__ r2u) {
    int i = blockIdx.x * blockDim.x + threadIdx.x;
    if (i < FS) {
        int a = sf[3*i+0], b = sf[3*i+1], c = sf[3*i+2];
        float x = (sv[3*a+0] + sv[3*b+0] + sv[3*c+0]) * (1.0f/3.0f);
        float y = (sv[3*a+1] + sv[3*b+1] + sv[3*c+1]) * (1.0f/3.0f);
        float z = (sv[3*a+2] + sv[3*b+2] + sv[3*c+2]) * (1.0f/3.0f);
        g_src_bc[i] = make_float4(x, y, z, 0.5f*(x*x + y*y + z*z));
        int ta = tf[i], tb = tf[FT + i], tc = tf[2*FT + i];
        float tx = (tv[3*ta+0] + tv[3*tb+0] + tv[3*tc+0]) * (1.0f/3.0f);
        float ty = (tv[3*ta+1] + tv[3*tb+1] + tv[3*tc+1]) * (1.0f/3.0f);
        float tz = (tv[3*ta+2] + tv[3*tb+2] + tv[3*tc+2]) * (1.0f/3.0f);
        g_tgt_bc[i] = make_float4(tx, ty, tz, 0.5f*(tx*tx + ty*ty + tz*tz));
    }
    if (i < NPTS) {
        int f = i >> 3;
        int a = sf[3*f+0], b = sf[3*f+1], c = sf[3*f+2];
        float r1 = sqrtf(r1u[i]);
        float r2 = r2u[i];
        float w1 = 1.0f - r1;
        float w2 = r1 * (1.0f - r2);
        float w3 = r1 * r2;
        float x = w1*sv[3*a+0] + w2*sv[3*b+0] + w3*sv[3*c+0];
        float y = w1*sv[3*a+1] + w2*sv[3*b+1] + w3*sv[3*c+1];
        float z = w1*sv[3*a+2] + w2*sv[3*b+2] + w3*sv[3*c+2];
        g_pts[i] = make_float4(x, y, z, x*x + y*y + z*z);
    }
}

// Pack candidate array into pair-interleaved u64x2 layout in shared:
//   pair t -> s[2t] = {pack(x0,x1), pack(y0,y1)}, s[2t+1] = {pack(z0,z1), pack(w0,w1)}
__device__ __forceinline__ void load_packed(ulonglong2* s, const float4* g, int tid, int tpb) {
    for (int t = tid; t < FS/2; t += tpb) {
        float4 a = g[2*t], b = g[2*t+1];
        ulonglong2 u0, u1;
        u0.x = pk2(a.x, b.x); u0.y = pk2(a.y, b.y);
        u1.x = pk2(a.z, b.z); u1.y = pk2(a.w, b.w);
        s[2*t]   = u0;
        s[2*t+1] = u1;
    }
}

// ---------------------------------------------------------------------------
// Kernel 2: reverse target min — one thread per point, packed FFMA2 loop.
// ---------------------------------------------------------------------------
__global__ void rev_tgt_kernel() {
    extern __shared__ ulonglong2 s_pk[];   // FT entries = 64 KB
    int tid = threadIdx.x;
    load_packed(s_pk, g_tgt_bc, tid, REV_TPB);
    __syncthreads();

    int i    = blockIdx.x * REV_TPB + tid;
    float4 p = g_pts[i];
    u64 npx = pk2(-p.x, -p.x);
    u64 npy = pk2(-p.y, -p.y);
    u64 npz = pk2(-p.z, -p.z);

    float m0 = 1e30f, m1 = 1e30f, m2 = 1e30f, m3 = 1e30f;
    #pragma unroll 4
    for (int t = 0; t < FT/4; t++) {
        ulonglong2 A = s_pk[4*t+0], B = s_pk[4*t+1];
        ulonglong2 C = s_pk[4*t+2], D = s_pk[4*t+3];
        u64 d0 = fma2(npx, A.x, fma2(npy, A.y, fma2(npz, B.x, B.y)));
        u64 d1 = fma2(npx, C.x, fma2(npy, C.y, fma2(npz, D.x, D.y)));
        float e0, e1, e2, e3;
        upk2(d0, e0, e1); upk2(d1, e2, e3);
        m0 = fminf(m0, e0); m1 = fminf(m1, e1);
        m2 = fminf(m2, e2); m3 = fminf(m3, e3);
    }
    g_mte[i] = fminf(fminf(m0, m1), fminf(m2, m3));
}

// ---------------------------------------------------------------------------
// Kernel 3: reverse source top-6 + final per-point value.
// Chunk-of-8 min gating: branch once per 8 candidates.
// ---------------------------------------------------------------------------
__global__ void rev_src_kernel(const float* __restrict__ probs) {
    extern __shared__ char smem_raw[];
    ulonglong2* s_pk = (ulonglong2*)smem_raw;       // FS entries = 64 KB
    float*      s_pr = (float*)(s_pk + FS);         // 16 KB

    int tid = threadIdx.x;
    load_packed(s_pk, g_src_bc, tid, REV_TPB);
    for (int k = tid; k < FS; k += REV_TPB) s_pr[k] = probs[k];
    __syncthreads();

    int i     = blockIdx.x * REV_TPB + tid;
    float4 p  = g_pts[i];
    int sface = i >> 3;
    u64 npx = pk2(-p.x, -p.x);
    u64 npy = pk2(-p.y, -p.y);
    u64 npz = pk2(-p.z, -p.z);

    float be[6]; int bi[6];
    #pragma unroll
    for (int k = 0; k < 6; k++) { be[k] = 1e30f; bi[k] = -1; }

    for (int c = 0; c < FS/8; c++) {            // 512 chunks of 8 candidates
        ulonglong2 A = s_pk[8*c+0], B = s_pk[8*c+1];
        ulonglong2 C = s_pk[8*c+2], D = s_pk[8*c+3];
        ulonglong2 E = s_pk[8*c+4], F = s_pk[8*c+5];
        ulonglong2 G = s_pk[8*c+6], H = s_pk[8*c+7];
        u64 d0 = fma2(npx, A.x, fma2(npy, A.y, fma2(npz, B.x, B.y)));
        u64 d1 = fma2(npx, C.x, fma2(npy, C.y, fma2(npz, D.x, D.y)));
        u64 d2 = fma2(npx, E.x, fma2(npy, E.y, fma2(npz, F.x, F.y)));
        u64 d3 = fma2(npx, G.x, fma2(npy, G.y, fma2(npz, H.x, H.y)));
        float e0, e1, e2, e3, e4, e5, e6, e7;
        upk2(d0, e0, e1); upk2(d1, e2, e3);
        upk2(d2, e4, e5); upk2(d3, e6, e7);
        float m = fminf(fminf(fminf(e0, e1), fminf(e2, e3)),
                        fminf(fminf(e4, e5), fminf(e6, e7)));
        if (m < be[5]) {                        // rare after warm-up
            int j = 8*c;
            try_insert(e0, j+0, be, bi);
            try_insert(e1, j+1, be, bi);
            try_insert(e2, j+2, be, bi);
            try_insert(e3, j+3, be, bi);
            try_insert(e4, j+4, be, bi);
            try_insert(e5, j+5, be, bi);
            try_insert(e6, j+6, be, bi);
            try_insert(e7, j+7, be, bi);
        }
    }

    // self-exclusion + weighted mean of valid 5
    int selfpos = 6;
    #pragma unroll
    for (int k = 0; k < 6; k++) if (bi[k] == sface) selfpos = k;
    float s5 = 0.0f;
    #pragma unroll
    for (int k = 0; k < 6; k++) {
        bool inc = (k != selfpos) && (k < 5 || selfpos <= 5);
        if (inc) {
            float d = fmaxf(fmaf(2.0f, be[k], p.w), 0.0f);
            s5 += s_pr[bi[k]] * d;
        }
    }
    float pp   = s_pr[sface];
    float mind = fmaxf(fmaf(2.0f, g_mte[i], p.w), 0.0f);
    float val  = fmaf(pp, mind, (1.0f - pp) * (s5 * 0.2f));

    __shared__ float red[REV_TPB];
    red[tid] = val;
    __syncthreads();
    #pragma unroll
    for (int s = REV_TPB/2; s > 0; s >>= 1) {
        if (tid < s) red[tid] += red[tid + s];
        __syncthreads();
    }
    if (tid == 0) g_rev_partial[blockIdx.x] = red[0];
}

// ---------------------------------------------------------------------------
// Kernel 4: forward loss (8 lanes per source face)
// ---------------------------------------------------------------------------
__global__ void fwd_kernel(const float* __restrict__ probs) {
    extern __shared__ float4 s_tgt[];   // FT float4 = 64 KB
    int tid = threadIdx.x;
    for (int k = tid; k < FT; k += TPB) s_tgt[k] = g_tgt_bc[k];
    __syncthreads();

    int gid   = blockIdx.x * TPB + tid;
    int face  = gid >> 3;
    int chunk = gid & 7;
    float4 p  = g_src_bc[face];           // p.w = 0.5*|p|^2

    float beste = 1e30f;
    #pragma unroll 8
    for (int t = 0; t < FT/8; t++) {
        float4 q = s_tgt[chunk + 8*t];
        float e = fmaf(-p.x, q.x, fmaf(-p.y, q.y, fmaf(-p.z, q.z, q.w)));
        beste = fminf(beste, e);
    }
    beste = fminf(beste, __shfl_xor_sync(0xffffffffu, beste, 1));
    beste = fminf(beste, __shfl_xor_sync(0xffffffffu, beste, 2));
    beste = fminf(beste, __shfl_xor_sync(0xffffffffu, beste, 4));

    float contrib = 0.0f;
    if (chunk == 0) {
        float d = fmaxf(2.0f * (p.w + beste), 0.0f);
        contrib = probs[face] * d;
    }
    __shared__ float red[TPB];
    red[tid] = contrib;
    __syncthreads();
    #pragma unroll
    for (int s = TPB/2; s > 0; s >>= 1) {
        if (tid < s) red[tid] += red[tid + s];
        __syncthreads();
    }
    if (tid == 0) g_fwd_partial[blockIdx.x] = red[0];
}

// ---------------------------------------------------------------------------
// Kernel 5: deterministic final reduction
// ---------------------------------------------------------------------------
__global__ void final_kernel(float* __restrict__ out) {
    __shared__ float red[TPB];
    int t = threadIdx.x;
    float v = g_rev_partial[t];
    if (t < FWD_BLK) v += g_fwd_partial[t];
    red[t] = v;
    __syncthreads();
    #pragma unroll
    for (int s = TPB/2; s > 0; s >>= 1) {
        if (t < s) red[t] += red[t + s];
        __syncthreads();
    }
    if (t == 0) out[0] = red[0];
}

extern "C" void kernel_launch(void* const* d_in, const int* in_sizes, int n_in,
                              void* d_out, int out_size) {
    const float* sv    = (const float*)d_in[0];
    const int*   sf    = (const int*)  d_in[1];
    const float* tv    = (const float*)d_in[2];
    const int*   tf    = (const int*)  d_in[3];
    const float* probs = (const float*)d_in[4];
    const float* r1u   = (const float*)d_in[5];
    const float* r2u   = (const float*)d_in[6];

    const size_t tgt_smem = (size_t)FT * sizeof(ulonglong2);                       // 64 KB
    const size_t src_smem = (size_t)FS * sizeof(ulonglong2) + FS * sizeof(float);  // 80 KB
    const size_t fwd_smem = (size_t)FT * sizeof(float4);                           // 64 KB
    cudaFuncSetAttribute(rev_tgt_kernel, cudaFuncAttributeMaxDynamicSharedMemorySize, (int)tgt_smem);
    cudaFuncSetAttribute(rev_src_kernel, cudaFuncAttributeMaxDynamicSharedMemorySize, (int)src_smem);
    cudaFuncSetAttribute(fwd_kernel,     cudaFuncAttributeMaxDynamicSharedMemorySize, (int)fwd_smem);

    prep_kernel   <<<NPTS / TPB, TPB>>>(sv, sf, tv, tf, r1u, r2u);
    rev_tgt_kernel<<<REV_BLK, REV_TPB, tgt_smem>>>();
    rev_src_kernel<<<REV_BLK, REV_TPB, src_smem>>>(probs);
    fwd_kernel    <<<FWD_BLK, TPB, fwd_smem>>>(probs);
    final_kernel  <<<1, TPB>>>((float*)d_out);
}